// round 1
// baseline (speedup 1.0000x reference)
#include <cuda_runtime.h>
#include <math.h>

// Problem constants
#define BB   4
#define CC   64
#define C2C  32
#define HH   48
#define WWD  48
#define HWN  2304          // 48*48
#define LT   7470          // total key positions across 5 scales
#define LPD  7488          // L padded to multiple of 64
#define KP   288           // 32*9 (QK patch dim)
#define NR   576           // 64*9 (value patch dim)

__constant__ int   c_off[5]   = {0, 2304, 4153, 5597, 6686};
__constant__ int   c_size[5]  = {48, 43, 38, 33, 28};
__constant__ float c_scale[5] = {1.0f, 0.9f, 0.8f, 0.7f, 0.6f};

// Scratch (static device globals; no allocation)
__device__ float g_mb [(size_t)BB * C2C * HWN];
__device__ float g_ref[(size_t)BB * CC  * LT];
__device__ float g_fm [(size_t)BB * C2C * LT];
__device__ float g_fa [(size_t)BB * CC  * LT];
__device__ float g_Wn [(size_t)BB * LPD * KP];
__device__ float g_R  [(size_t)BB * LPD * NR];
__device__ float g_P  [(size_t)BB * HWN * KP];
__device__ float g_S  [(size_t)BB * HWN * LPD];   // score, then attn (in place)
__device__ float g_G  [(size_t)BB * HWN * NR];

__device__ __forceinline__ float prelu(float v, float a) {
    return v >= 0.f ? v : a * v;
}

// torch bicubic kernel, A = -0.75
__device__ __forceinline__ float cubicw(float x) {
    x = fabsf(x);
    if (x <= 1.f)  return (1.25f * x - 2.25f) * x * x + 1.f;
    if (x <  2.f)  return ((-0.75f * x + 3.75f) * x - 6.f) * x + 3.f;
    return 0.f;
}

__device__ __forceinline__ int find_scale(int l) {
    if (l < c_off[1]) return 0;
    if (l < c_off[2]) return 1;
    if (l < c_off[3]) return 2;
    if (l < c_off[4]) return 3;
    return 4;
}

__device__ __forceinline__ float warp_sum(float v) {
    #pragma unroll
    for (int o = 16; o > 0; o >>= 1) v += __shfl_down_sync(0xffffffffu, v, o);
    return v;
}
__device__ __forceinline__ float warp_max(float v) {
    #pragma unroll
    for (int o = 16; o > 0; o >>= 1) v = fmaxf(v, __shfl_down_sync(0xffffffffu, v, o));
    return v;
}

// ---------------------------------------------------------------------------
// 1. match_base = prelu(w_mb @ x + b_mb)  -> [B, 32, 2304]
// ---------------------------------------------------------------------------
__global__ void k_mb(const float* __restrict__ x, const float* __restrict__ w,
                     const float* __restrict__ b, const float* __restrict__ a) {
    int idx = blockIdx.x * blockDim.x + threadIdx.x;
    if (idx >= BB * C2C * HWN) return;
    int p  = idx % HWN;
    int t  = idx / HWN;
    int c2 = t % C2C;
    int bb = t / C2C;
    const float* xb = x + (size_t)bb * CC * HWN;
    float s = b[c2];
    #pragma unroll 8
    for (int c = 0; c < CC; c++) s = fmaf(w[c2 * CC + c], xb[(size_t)c * HWN + p], s);
    g_mb[idx] = prelu(s, a[0]);
}

// ---------------------------------------------------------------------------
// 2. Build pyramid ref images (bicubic downsample; scale 0 = identity copy)
// ---------------------------------------------------------------------------
__global__ void k_ref(const float* __restrict__ x) {
    int idx = blockIdx.x * blockDim.x + threadIdx.x;
    if (idx >= BB * CC * LT) return;
    int l  = idx % LT;
    int t  = idx / LT;
    int c  = t % CC;
    int bb = t / CC;
    int s  = find_scale(l);
    int ll = l - c_off[s];
    const float* xb = x + ((size_t)bb * CC + c) * HWN;
    float out;
    if (s == 0) {
        out = xb[ll];
    } else {
        int n  = c_size[s];
        int oh = ll / n, ow = ll % n;
        float sc   = c_scale[s];
        float srcy = (oh + 0.5f) / sc - 0.5f;
        float srcx = (ow + 0.5f) / sc - 0.5f;
        int   fy = (int)floorf(srcy);
        int   fx = (int)floorf(srcx);
        float fry = srcy - fy, frx = srcx - fx;
        float wy[4], wx[4];
        #pragma unroll
        for (int k = 0; k < 4; k++) {
            wy[k] = cubicw((float)(k - 1) - fry);
            wx[k] = cubicw((float)(k - 1) - frx);
        }
        out = 0.f;
        #pragma unroll
        for (int ky = 0; ky < 4; ky++) {
            int iy = min(max(fy + ky - 1, 0), HH - 1);
            float acc = 0.f;
            #pragma unroll
            for (int kx = 0; kx < 4; kx++) {
                int ix = min(max(fx + kx - 1, 0), WWD - 1);
                acc = fmaf(wx[kx], xb[iy * WWD + ix], acc);
            }
            out = fmaf(wy[ky], acc, out);
        }
    }
    g_ref[idx] = out;
}

// ---------------------------------------------------------------------------
// 3. 1x1 conv + PReLU over concatenated pyramid (which=0 -> fm[32], 1 -> fa[64])
// ---------------------------------------------------------------------------
__global__ void k_conv1(const float* __restrict__ w, const float* __restrict__ b,
                        const float* __restrict__ a, int cout, int which) {
    int idx = blockIdx.x * blockDim.x + threadIdx.x;
    if (idx >= BB * cout * LT) return;
    int l  = idx % LT;
    int t  = idx / LT;
    int co = t % cout;
    int bb = t / cout;
    const float* rb = g_ref + (size_t)bb * CC * LT;
    float s = b[co];
    #pragma unroll 8
    for (int c = 0; c < CC; c++) s = fmaf(w[co * CC + c], rb[(size_t)c * LT + l], s);
    s = prelu(s, a[0]);
    if (which == 0) g_fm[idx] = s; else g_fa[idx] = s;
}

// ---------------------------------------------------------------------------
// 4. Query patches: P[b, p, c2*9+i*3+j] from match_base (zero pad)
// ---------------------------------------------------------------------------
__global__ void k_P() {
    int idx = blockIdx.x * blockDim.x + threadIdx.x;
    if (idx >= BB * HWN * KP) return;
    int e  = idx % KP;
    int t  = idx / KP;
    int p  = t % HWN;
    int bb = t / HWN;
    int c2 = e / 9, r = e % 9;
    int di = r / 3 - 1, dj = r % 3 - 1;
    int h = p / WWD + di, w = p % WWD + dj;
    float v = 0.f;
    if (h >= 0 && h < HH && w >= 0 && w < WWD)
        v = g_mb[((size_t)bb * C2C + c2) * HWN + h * WWD + w];
    g_P[idx] = v;
}

// ---------------------------------------------------------------------------
// 5. Key filters: gather fm patch, L2-normalize (escape_nan), pad rows -> 0
//    one block (128 threads) per (b, l)
// ---------------------------------------------------------------------------
__global__ void k_Wn(const float* __restrict__ esc) {
    int bl = blockIdx.x;
    int l  = bl % LPD;
    int bb = bl / LPD;
    float* out = g_Wn + ((size_t)bb * LPD + l) * KP;
    int tid = threadIdx.x;
    if (l >= LT) {
        for (int e = tid; e < KP; e += 128) out[e] = 0.f;
        return;
    }
    __shared__ float buf[KP];
    __shared__ float red[4];
    int s  = find_scale(l);
    int ll = l - c_off[s];
    int n  = c_size[s];
    int hl = ll / n, wl = ll % n;
    int base = c_off[s];
    float local = 0.f;
    for (int e = tid; e < KP; e += 128) {
        int c2 = e / 9, r = e % 9;
        int hh = hl + r / 3 - 1, ww = wl + r % 3 - 1;
        float v = 0.f;
        if (hh >= 0 && hh < n && ww >= 0 && ww < n)
            v = g_fm[((size_t)bb * C2C + c2) * LT + base + hh * n + ww];
        buf[e] = v;
        local += v * v;
    }
    local = warp_sum(local);
    if ((tid & 31) == 0) red[tid >> 5] = local;
    __syncthreads();
    float tot = red[0] + red[1] + red[2] + red[3];
    float inv = 1.f / fmaxf(sqrtf(tot), esc[0]);
    for (int e = tid; e < KP; e += 128) out[e] = buf[e] * inv;
}

// ---------------------------------------------------------------------------
// 6. Value patches: R[b, l, c*9+u*3+v] from fa (zero pad); pad rows -> 0
// ---------------------------------------------------------------------------
__global__ void k_R() {
    size_t idx = (size_t)blockIdx.x * blockDim.x + threadIdx.x;
    if (idx >= (size_t)BB * LPD * NR) return;
    int e  = (int)(idx % NR);
    size_t t = idx / NR;
    int l  = (int)(t % LPD);
    int bb = (int)(t / LPD);
    float v = 0.f;
    if (l < LT) {
        int s  = find_scale(l);
        int ll = l - c_off[s];
        int n  = c_size[s];
        int hl = ll / n, wl = ll % n;
        int c = e / 9, r = e % 9;
        int hh = hl + r / 3 - 1, ww = wl + r % 3 - 1;
        if (hh >= 0 && hh < n && ww >= 0 && ww < n)
            v = g_fa[((size_t)bb * CC + c) * LT + c_off[s] + hh * n + ww];
    }
    g_R[idx] = v;
}

// ---------------------------------------------------------------------------
// 7. GEMM-NT: S[2304, LPD] = P[2304, 288] @ Wn[LPD, 288]^T   (per batch)
// ---------------------------------------------------------------------------
#define TKK 16
__global__ void k_gemm_nt() {
    int bb = blockIdx.z;
    const float* A = g_P  + (size_t)bb * HWN * KP;
    const float* Bm = g_Wn + (size_t)bb * LPD * KP;
    float* Cm = g_S + (size_t)bb * HWN * LPD;
    int m0 = blockIdx.y * 64, n0 = blockIdx.x * 64;
    __shared__ float As[64][TKK + 1];
    __shared__ float Bs[64][TKK + 1];
    float acc[4][4] = {};
    int tid = threadIdx.y * 16 + threadIdx.x;
    for (int k0 = 0; k0 < KP; k0 += TKK) {
        #pragma unroll
        for (int t = 0; t < 4; t++) {
            int e = tid + t * 256;
            int r = e / TKK, kk = e % TKK;
            As[r][kk] = A[(size_t)(m0 + r) * KP + k0 + kk];
        }
        #pragma unroll
        for (int t = 0; t < 4; t++) {
            int e = tid + t * 256;
            int r = e / TKK, kk = e % TKK;
            Bs[r][kk] = Bm[(size_t)(n0 + r) * KP + k0 + kk];
        }
        __syncthreads();
        #pragma unroll
        for (int kk = 0; kk < TKK; kk++) {
            float av[4], bv[4];
            #pragma unroll
            for (int i = 0; i < 4; i++) av[i] = As[threadIdx.y * 4 + i][kk];
            #pragma unroll
            for (int j = 0; j < 4; j++) bv[j] = Bs[threadIdx.x * 4 + j][kk];
            #pragma unroll
            for (int i = 0; i < 4; i++)
                #pragma unroll
                for (int j = 0; j < 4; j++) acc[i][j] = fmaf(av[i], bv[j], acc[i][j]);
        }
        __syncthreads();
    }
    #pragma unroll
    for (int i = 0; i < 4; i++)
        #pragma unroll
        for (int j = 0; j < 4; j++)
            Cm[(size_t)(m0 + threadIdx.y * 4 + i) * LPD + n0 + threadIdx.x * 4 + j] = acc[i][j];
}

// ---------------------------------------------------------------------------
// 8. Row softmax over l<LT of 10*S; pad columns -> 0. One block per row.
// ---------------------------------------------------------------------------
__global__ void k_softmax() {
    size_t row = blockIdx.x;                     // b*HWN + p
    float* S = g_S + row * LPD;
    __shared__ float buf[LT];
    __shared__ float red[8];
    int tid = threadIdx.x;
    float mx = -1e30f;
    for (int l = tid; l < LT; l += 256) {
        float v = S[l];
        buf[l] = v;
        mx = fmaxf(mx, v);
    }
    mx = warp_max(mx);
    if ((tid & 31) == 0) red[tid >> 5] = mx;
    __syncthreads();
    if (tid < 8) {
        float v = red[tid];
        #pragma unroll
        for (int o = 4; o > 0; o >>= 1) v = fmaxf(v, __shfl_down_sync(0xffu, v, o));
        if (tid == 0) red[0] = v;
    }
    __syncthreads();
    mx = red[0];
    __syncthreads();
    float sum = 0.f;
    for (int l = tid; l < LT; l += 256) {
        float e = expf(10.f * (buf[l] - mx));
        buf[l] = e;
        sum += e;
    }
    sum = warp_sum(sum);
    if ((tid & 31) == 0) red[tid >> 5] = sum;
    __syncthreads();
    if (tid < 8) {
        float v = red[tid];
        #pragma unroll
        for (int o = 4; o > 0; o >>= 1) v += __shfl_down_sync(0xffu, v, o);
        if (tid == 0) red[0] = v;
    }
    __syncthreads();
    float inv = 1.f / red[0];
    for (int l = tid; l < LT; l += 256) S[l] = buf[l] * inv;
    if (tid < LPD - LT) S[LT + tid] = 0.f;
}

// ---------------------------------------------------------------------------
// 9. GEMM-NN: G[2304, 576] = A[2304, LPD] @ R[LPD, 576]   (per batch)
// ---------------------------------------------------------------------------
__global__ void k_gemm_nn() {
    int bb = blockIdx.z;
    const float* A  = g_S + (size_t)bb * HWN * LPD;
    const float* Bm = g_R + (size_t)bb * LPD * NR;
    float* Cm = g_G + (size_t)bb * HWN * NR;
    int m0 = blockIdx.y * 64, n0 = blockIdx.x * 64;
    __shared__ float As[64][TKK + 1];
    __shared__ float Bs[TKK][64 + 1];
    float acc[4][4] = {};
    int tid = threadIdx.y * 16 + threadIdx.x;
    for (int k0 = 0; k0 < LPD; k0 += TKK) {
        #pragma unroll
        for (int t = 0; t < 4; t++) {
            int e = tid + t * 256;
            int r = e / TKK, kk = e % TKK;
            As[r][kk] = A[(size_t)(m0 + r) * LPD + k0 + kk];
        }
        #pragma unroll
        for (int t = 0; t < 4; t++) {
            int e = tid + t * 256;
            int r = e / 64, c = e % 64;
            Bs[r][c] = Bm[(size_t)(k0 + r) * NR + n0 + c];
        }
        __syncthreads();
        #pragma unroll
        for (int kk = 0; kk < TKK; kk++) {
            float av[4], bv[4];
            #pragma unroll
            for (int i = 0; i < 4; i++) av[i] = As[threadIdx.y * 4 + i][kk];
            #pragma unroll
            for (int j = 0; j < 4; j++) bv[j] = Bs[kk][threadIdx.x * 4 + j];
            #pragma unroll
            for (int i = 0; i < 4; i++)
                #pragma unroll
                for (int j = 0; j < 4; j++) acc[i][j] = fmaf(av[i], bv[j], acc[i][j]);
        }
        __syncthreads();
    }
    #pragma unroll
    for (int i = 0; i < 4; i++)
        #pragma unroll
        for (int j = 0; j < 4; j++)
            Cm[(size_t)(m0 + threadIdx.y * 4 + i) * NR + n0 + threadIdx.x * 4 + j] = acc[i][j];
}

// ---------------------------------------------------------------------------
// 10. Output: 9-tap gather of G (conv_transpose collapse) /4 + residual
// ---------------------------------------------------------------------------
__global__ void k_out(const float* __restrict__ x, float* __restrict__ out) {
    int idx = blockIdx.x * blockDim.x + threadIdx.x;
    if (idx >= BB * CC * HWN) return;
    int p  = idx % HWN;
    int t  = idx / HWN;
    int c  = t % CC;
    int bb = t / CC;
    int h = p / WWD, w = p % WWD;
    float s = 0.f;
    #pragma unroll
    for (int dy = -1; dy <= 1; dy++) {
        int hh = h + dy;
        if (hh < 0 || hh >= HH) continue;
        #pragma unroll
        for (int dx = -1; dx <= 1; dx++) {
            int ww = w + dx;
            if (ww < 0 || ww >= WWD) continue;
            int q = hh * WWD + ww;
            int u = 1 - dy, v = 1 - dx;
            s += g_G[((size_t)bb * HWN + q) * NR + c * 9 + u * 3 + v];
        }
    }
    out[idx] = x[idx] + 0.25f * s;
}

// ---------------------------------------------------------------------------
extern "C" void kernel_launch(void* const* d_in, const int* in_sizes, int n_in,
                              void* d_out, int out_size) {
    const float* x    = (const float*)d_in[0];
    const float* w_mb = (const float*)d_in[1];
    const float* b_mb = (const float*)d_in[2];
    const float* a_mb = (const float*)d_in[3];
    const float* w_m  = (const float*)d_in[4];
    const float* b_m  = (const float*)d_in[5];
    const float* a_m  = (const float*)d_in[6];
    const float* w_a  = (const float*)d_in[7];
    const float* b_a  = (const float*)d_in[8];
    const float* a_a  = (const float*)d_in[9];
    const float* esc  = (const float*)d_in[10];
    float* out = (float*)d_out;

    int n;
    n = BB * C2C * HWN;
    k_mb<<<(n + 255) / 256, 256>>>(x, w_mb, b_mb, a_mb);

    n = BB * CC * LT;
    k_ref<<<(n + 255) / 256, 256>>>(x);

    n = BB * C2C * LT;
    k_conv1<<<(n + 255) / 256, 256>>>(w_m, b_m, a_m, C2C, 0);
    n = BB * CC * LT;
    k_conv1<<<(n + 255) / 256, 256>>>(w_a, b_a, a_a, CC, 1);

    n = BB * HWN * KP;
    k_P<<<(n + 255) / 256, 256>>>();

    k_Wn<<<BB * LPD, 128>>>(esc);

    {
        size_t tot = (size_t)BB * LPD * NR;
        k_R<<<(unsigned)((tot + 255) / 256), 256>>>();
    }

    {
        dim3 grid(LPD / 64, HWN / 64, BB), block(16, 16);
        k_gemm_nt<<<grid, block>>>();
    }

    k_softmax<<<BB * HWN, 256>>>();

    {
        dim3 grid(NR / 64, HWN / 64, BB), block(16, 16);
        k_gemm_nn<<<grid, block>>>();
    }

    n = BB * CC * HWN;
    k_out<<<(n + 255) / 256, 256>>>(x, out);
}

// round 3
// speedup vs baseline: 2.8626x; 2.8626x over previous
#include <cuda_runtime.h>
#include <math.h>

// Problem constants
#define BB   4
#define CC   64
#define C2C  32
#define HH   48
#define WWD  48
#define HWN  2304          // 48*48
#define LT   7470          // total key positions across 5 scales
#define LPD  7488          // L padded to multiple of 64

__constant__ int   c_off[5]   = {0, 2304, 4153, 5597, 6686};
__constant__ int   c_size[5]  = {48, 43, 38, 33, 28};
__constant__ float c_scale[5] = {1.0f, 0.9f, 0.8f, 0.7f, 0.6f};

// Scratch (static device globals; no allocation)
__device__ float g_mb  [(size_t)BB * C2C * HWN];
__device__ float g_ref [(size_t)BB * CC  * LT];
__device__ float g_fm  [(size_t)BB * C2C * LT];
__device__ float g_fa  [(size_t)BB * CC  * LT];
__device__ float g_E   [(size_t)BB * LT];
__device__ float g_inv [(size_t)BB * LT];          // 10 / max(norm, esc)
__device__ int   g_meta[LT];
__device__ float g_D   [(size_t)BB * HWN * LPD];   // D = mb^T * fm
__device__ float g_A   [(size_t)BB * HWN * LPD];   // attention weights
__device__ float g_At  [(size_t)BB * HWN * LPD];   // blurred attention

__device__ __forceinline__ float prelu(float v, float a) {
    return v >= 0.f ? v : a * v;
}

__device__ __forceinline__ float cubicw(float x) {   // torch bicubic, A=-0.75
    x = fabsf(x);
    if (x <= 1.f)  return (1.25f * x - 2.25f) * x * x + 1.f;
    if (x <  2.f)  return ((-0.75f * x + 3.75f) * x - 6.f) * x + 3.f;
    return 0.f;
}

__device__ __forceinline__ int find_scale(int l) {
    if (l < c_off[1]) return 0;
    if (l < c_off[2]) return 1;
    if (l < c_off[3]) return 2;
    if (l < c_off[4]) return 3;
    return 4;
}

__device__ __forceinline__ float warp_sum(float v) {
    #pragma unroll
    for (int o = 16; o > 0; o >>= 1) v += __shfl_down_sync(0xffffffffu, v, o);
    return v;
}
__device__ __forceinline__ float warp_max(float v) {
    #pragma unroll
    for (int o = 16; o > 0; o >>= 1) v = fmaxf(v, __shfl_down_sync(0xffffffffu, v, o));
    return v;
}

// ---------------------------------------------------------------------------
// 0. Per-l metadata: scale width n + scale-grid boundary validity bits
//    bit8: hl>0, bit9: hl<n-1, bit10: wl>0, bit11: wl<n-1
// ---------------------------------------------------------------------------
__global__ void k_meta() {
    int l = blockIdx.x * 256 + threadIdx.x;
    if (l >= LT) return;
    int s  = find_scale(l);
    int ll = l - c_off[s];
    int n  = c_size[s];
    int hl = ll / n, wl = ll - hl * n;
    int m = n;
    if (hl > 0)     m |= 1 << 8;
    if (hl < n - 1) m |= 1 << 9;
    if (wl > 0)     m |= 1 << 10;
    if (wl < n - 1) m |= 1 << 11;
    g_meta[l] = m;
}

// ---------------------------------------------------------------------------
// 1. match_base = prelu(w_mb @ x + b_mb) -> [B, 32, 2304]
// ---------------------------------------------------------------------------
__global__ void k_mb(const float* __restrict__ x, const float* __restrict__ w,
                     const float* __restrict__ b, const float* __restrict__ a) {
    int idx = blockIdx.x * blockDim.x + threadIdx.x;
    if (idx >= BB * C2C * HWN) return;
    int p  = idx % HWN;
    int t  = idx / HWN;
    int c2 = t % C2C;
    int bb = t / C2C;
    const float* xb = x + (size_t)bb * CC * HWN;
    float s = b[c2];
    #pragma unroll 8
    for (int c = 0; c < CC; c++) s = fmaf(w[c2 * CC + c], xb[(size_t)c * HWN + p], s);
    g_mb[idx] = prelu(s, a[0]);
}

// ---------------------------------------------------------------------------
// 2. Pyramid ref images (bicubic downsample; scale 0 = identity copy)
// ---------------------------------------------------------------------------
__global__ void k_ref(const float* __restrict__ x) {
    int idx = blockIdx.x * blockDim.x + threadIdx.x;
    if (idx >= BB * CC * LT) return;
    int l  = idx % LT;
    int t  = idx / LT;
    int c  = t % CC;
    int bb = t / CC;
    int s  = find_scale(l);
    int ll = l - c_off[s];
    const float* xb = x + ((size_t)bb * CC + c) * HWN;
    float out;
    if (s == 0) {
        out = xb[ll];
    } else {
        int n  = c_size[s];
        int oh = ll / n, ow = ll % n;
        float sc   = c_scale[s];
        float srcy = (oh + 0.5f) / sc - 0.5f;
        float srcx = (ow + 0.5f) / sc - 0.5f;
        int   fy = (int)floorf(srcy);
        int   fx = (int)floorf(srcx);
        float fry = srcy - fy, frx = srcx - fx;
        float wy[4], wx[4];
        #pragma unroll
        for (int k = 0; k < 4; k++) {
            wy[k] = cubicw((float)(k - 1) - fry);
            wx[k] = cubicw((float)(k - 1) - frx);
        }
        out = 0.f;
        #pragma unroll
        for (int ky = 0; ky < 4; ky++) {
            int iy = min(max(fy + ky - 1, 0), HH - 1);
            float acc = 0.f;
            #pragma unroll
            for (int kx = 0; kx < 4; kx++) {
                int ix = min(max(fx + kx - 1, 0), WWD - 1);
                acc = fmaf(wx[kx], xb[iy * WWD + ix], acc);
            }
            out = fmaf(wy[ky], acc, out);
        }
    }
    g_ref[idx] = out;
}

// ---------------------------------------------------------------------------
// 3. Both 1x1 convs over the pyramid in one pass (smem-tiled):
//    fm (32 ch, w_m) and fa (64 ch, w_a). Tile: 64 l-positions (40KB smem).
// ---------------------------------------------------------------------------
#define CT 64
__global__ void k_convs(const float* __restrict__ w_m, const float* __restrict__ b_m,
                        const float* __restrict__ a_m,
                        const float* __restrict__ w_a, const float* __restrict__ b_a,
                        const float* __restrict__ a_a) {
    __shared__ float sRef[CC][CT];
    __shared__ float sW[96][CC];
    int bb = blockIdx.y;
    int l0 = blockIdx.x * CT;
    int tid = threadIdx.x;
    for (int e = tid; e < 96 * CC; e += 256) {
        int co = e / CC, c = e % CC;
        sW[co][c] = (co < C2C) ? w_m[co * CC + c] : w_a[(co - C2C) * CC + c];
    }
    for (int e = tid; e < CC * CT; e += 256) {
        int c = e / CT, j = e % CT;
        sRef[c][j] = (l0 + j < LT) ? g_ref[((size_t)bb * CC + c) * LT + l0 + j] : 0.f;
    }
    __syncthreads();
    float am = a_m[0], aa = a_a[0];
    for (int o = tid; o < 96 * CT; o += 256) {
        int co = o / CT, j = o % CT;
        if (l0 + j >= LT) continue;
        float s = (co < C2C) ? b_m[co] : b_a[co - C2C];
        #pragma unroll 16
        for (int c = 0; c < CC; c++) s = fmaf(sW[co][c], sRef[c][j], s);
        if (co < C2C)
            g_fm[((size_t)bb * C2C + co) * LT + l0 + j] = prelu(s, am);
        else
            g_fa[((size_t)bb * CC + (co - C2C)) * LT + l0 + j] = prelu(s, aa);
    }
}

// ---------------------------------------------------------------------------
// 4. E[b,l] = sum_c2 fm^2  ;  then inv10 = 10 / max(sqrt(blur9(E)), esc)
// ---------------------------------------------------------------------------
__global__ void k_E() {
    int idx = blockIdx.x * 256 + threadIdx.x;
    if (idx >= BB * LT) return;
    int l = idx % LT, bb = idx / LT;
    float s = 0.f;
    #pragma unroll 8
    for (int c2 = 0; c2 < C2C; c2++) {
        float v = g_fm[((size_t)bb * C2C + c2) * LT + l];
        s = fmaf(v, v, s);
    }
    g_E[idx] = s;
}

__global__ void k_inv(const float* __restrict__ esc) {
    int idx = blockIdx.x * 256 + threadIdx.x;
    if (idx >= BB * LT) return;
    int l = idx % LT, bb = idx / LT;
    int m = g_meta[l];
    int n = m & 255;
    int my0 = (m >> 8) & 1, my2 = (m >> 9) & 1;
    int mx0 = (m >> 10) & 1, mx2 = (m >> 11) & 1;
    const float* E = g_E + (size_t)bb * LT;
    float s = 0.f;
    #pragma unroll
    for (int dy = 0; dy < 3; dy++) {
        int yok = (dy == 0) ? my0 : (dy == 2) ? my2 : 1;
        if (!yok) continue;
        #pragma unroll
        for (int dx = 0; dx < 3; dx++) {
            int xok = (dx == 0) ? mx0 : (dx == 2) ? mx2 : 1;
            if (!xok) continue;
            s += E[l + (dy - 1) * n + (dx - 1)];
        }
    }
    g_inv[idx] = 10.f / fmaxf(sqrtf(s), esc[0]);
}

// ---------------------------------------------------------------------------
// 5. D = mb^T * fm : [2304, LPD], K=32  (pad cols -> 0)
// ---------------------------------------------------------------------------
__global__ void k_D() {
    int bb = blockIdx.z;
    int m0 = blockIdx.y * 64, n0 = blockIdx.x * 64;
    __shared__ float As[C2C][65];
    __shared__ float Bs[C2C][65];
    int tid = threadIdx.y * 16 + threadIdx.x;
    #pragma unroll
    for (int t = 0; t < 8; t++) {
        int e = tid + t * 256;
        int k = e >> 6, col = e & 63;
        As[k][col] = g_mb[((size_t)bb * C2C + k) * HWN + m0 + col];
        Bs[k][col] = (n0 + col < LT) ? g_fm[((size_t)bb * C2C + k) * LT + n0 + col] : 0.f;
    }
    __syncthreads();
    float acc[4][4] = {};
    #pragma unroll
    for (int kk = 0; kk < C2C; kk++) {
        float av[4], bv[4];
        #pragma unroll
        for (int i = 0; i < 4; i++) av[i] = As[kk][threadIdx.y * 4 + i];
        #pragma unroll
        for (int j = 0; j < 4; j++) bv[j] = Bs[kk][threadIdx.x * 4 + j];
        #pragma unroll
        for (int i = 0; i < 4; i++)
            #pragma unroll
            for (int j = 0; j < 4; j++) acc[i][j] = fmaf(av[i], bv[j], acc[i][j]);
    }
    float* Dp = g_D + (size_t)bb * HWN * LPD;
    #pragma unroll
    for (int i = 0; i < 4; i++)
        #pragma unroll
        for (int j = 0; j < 4; j++)
            Dp[(size_t)(m0 + threadIdx.y * 4 + i) * LPD + n0 + threadIdx.x * 4 + j] = acc[i][j];
}

// ---------------------------------------------------------------------------
// 6. Fused: S row = inv10[l]*blur9(D) -> softmax -> A row.  1 block / (b,p)
// ---------------------------------------------------------------------------
__global__ void k_sm() {
    int bp = blockIdx.x;
    int p  = bp % HWN;
    int bb = bp / HWN;
    int h = p / WWD, w = p % WWD;
    int hy0 = (h > 0), hy2 = (h < HH - 1);
    int wx0 = (w > 0), wx2 = (w < WWD - 1);
    const float* D = g_D + (size_t)bb * HWN * LPD + (size_t)p * LPD;
    float* A = g_A + (size_t)bb * HWN * LPD + (size_t)p * LPD;
    const float* inv = g_inv + (size_t)bb * LT;

    __shared__ float buf[LT];
    __shared__ float red[8];
    int tid = threadIdx.x;
    float mx = -1e30f;
    for (int l = tid; l < LT; l += 256) {
        int m = g_meta[l];
        int n = m & 255;
        float acc = 0.f;
        #pragma unroll
        for (int dy = 0; dy < 3; dy++) {
            int yok = (dy == 0) ? (hy0 & ((m >> 8) & 1))
                    : (dy == 2) ? (hy2 & ((m >> 9) & 1)) : 1;
            if (!yok) continue;
            const float* Drow = D + (dy - 1) * WWD * LPD + (dy - 1) * n;
            #pragma unroll
            for (int dx = 0; dx < 3; dx++) {
                int xok = (dx == 0) ? (wx0 & ((m >> 10) & 1))
                        : (dx == 2) ? (wx2 & ((m >> 11) & 1)) : 1;
                if (!xok) continue;
                acc += Drow[(dx - 1) * LPD + l + (dx - 1)];
            }
        }
        float v = acc * inv[l];
        buf[l] = v;
        mx = fmaxf(mx, v);
    }
    mx = warp_max(mx);
    if ((tid & 31) == 0) red[tid >> 5] = mx;
    __syncthreads();
    if (tid < 8) {
        float v = red[tid];
        #pragma unroll
        for (int o = 4; o > 0; o >>= 1) v = fmaxf(v, __shfl_down_sync(0xffu, v, o));
        if (tid == 0) red[0] = v;
    }
    __syncthreads();
    mx = red[0];
    __syncthreads();
    float sum = 0.f;
    for (int l = tid; l < LT; l += 256) {
        float e = expf(buf[l] - mx);
        buf[l] = e;
        sum += e;
    }
    sum = warp_sum(sum);
    if ((tid & 31) == 0) red[tid >> 5] = sum;
    __syncthreads();
    if (tid < 8) {
        float v = red[tid];
        #pragma unroll
        for (int o = 4; o > 0; o >>= 1) v += __shfl_down_sync(0xffu, v, o);
        if (tid == 0) red[0] = v;
    }
    __syncthreads();
    float is = 1.f / red[0];
    for (int l = tid; l < LT; l += 256) A[l] = buf[l] * is;
}

// ---------------------------------------------------------------------------
// 7. At = blur9(A)  (masked diagonal blur; pad cols -> 0)
// ---------------------------------------------------------------------------
__global__ void k_blurA() {
    int l = blockIdx.x * 256 + threadIdx.x;
    if (l >= LPD) return;
    int p  = blockIdx.y;
    int bb = blockIdx.z;
    float* At = g_At + ((size_t)bb * HWN + p) * LPD;
    if (l >= LT) { At[l] = 0.f; return; }
    int h = p / WWD, w = p % WWD;
    int hy0 = (h > 0), hy2 = (h < HH - 1);
    int wx0 = (w > 0), wx2 = (w < WWD - 1);
    const float* A = g_A + (size_t)bb * HWN * LPD + (size_t)p * LPD;
    int m = g_meta[l];
    int n = m & 255;
    float acc = 0.f;
    #pragma unroll
    for (int dy = 0; dy < 3; dy++) {
        int yok = (dy == 0) ? (hy0 & ((m >> 8) & 1))
                : (dy == 2) ? (hy2 & ((m >> 9) & 1)) : 1;
        if (!yok) continue;
        const float* Arow = A + (dy - 1) * WWD * LPD + (dy - 1) * n;
        #pragma unroll
        for (int dx = 0; dx < 3; dx++) {
            int xok = (dx == 0) ? (wx0 & ((m >> 10) & 1))
                    : (dx == 2) ? (wx2 & ((m >> 11) & 1)) : 1;
            if (!xok) continue;
            acc += Arow[(dx - 1) * LPD + l + (dx - 1)];
        }
    }
    At[l] = acc;
}

// ---------------------------------------------------------------------------
// 8. Final GEMM + epilogue: y[b,c,p] = x + 0.25 * sum_l At[p,l]*fa[c,l]
//    M=2304 (tiles of 32), N=64 (all), K=LPD
// ---------------------------------------------------------------------------
#define TK2 16
__global__ void k_gemm2(const float* __restrict__ x, float* __restrict__ out) {
    int bb = blockIdx.y;
    int m0 = blockIdx.x * 32;
    __shared__ float As[32][TK2 + 1];
    __shared__ float Bs[64][TK2 + 1];
    int tid = threadIdx.y * 16 + threadIdx.x;
    const float* At = g_At + (size_t)bb * HWN * LPD;
    const float* fa = g_fa + (size_t)bb * CC * LT;
    float acc[2][4] = {};
    for (int k0 = 0; k0 < LPD; k0 += TK2) {
        #pragma unroll
        for (int t = 0; t < 2; t++) {
            int e = tid + t * 256;
            int r = e / TK2, kk = e % TK2;
            As[r][kk] = At[(size_t)(m0 + r) * LPD + k0 + kk];
        }
        #pragma unroll
        for (int t = 0; t < 4; t++) {
            int e = tid + t * 256;
            int r = e / TK2, kk = e % TK2;
            Bs[r][kk] = (k0 + kk < LT) ? fa[(size_t)r * LT + k0 + kk] : 0.f;
        }
        __syncthreads();
        #pragma unroll
        for (int kk = 0; kk < TK2; kk++) {
            float av[2], bv[4];
            #pragma unroll
            for (int i = 0; i < 2; i++) av[i] = As[threadIdx.y * 2 + i][kk];
            #pragma unroll
            for (int j = 0; j < 4; j++) bv[j] = Bs[threadIdx.x * 4 + j][kk];
            #pragma unroll
            for (int i = 0; i < 2; i++)
                #pragma unroll
                for (int j = 0; j < 4; j++) acc[i][j] = fmaf(av[i], bv[j], acc[i][j]);
        }
        __syncthreads();
    }
    #pragma unroll
    for (int i = 0; i < 2; i++) {
        int p = m0 + threadIdx.y * 2 + i;
        #pragma unroll
        for (int j = 0; j < 4; j++) {
            int c = threadIdx.x * 4 + j;
            size_t o = ((size_t)bb * CC + c) * HWN + p;
            out[o] = x[o] + 0.25f * acc[i][j];
        }
    }
}

// ---------------------------------------------------------------------------
extern "C" void kernel_launch(void* const* d_in, const int* in_sizes, int n_in,
                              void* d_out, int out_size) {
    const float* x    = (const float*)d_in[0];
    const float* w_mb = (const float*)d_in[1];
    const float* b_mb = (const float*)d_in[2];
    const float* a_mb = (const float*)d_in[3];
    const float* w_m  = (const float*)d_in[4];
    const float* b_m  = (const float*)d_in[5];
    const float* a_m  = (const float*)d_in[6];
    const float* w_a  = (const float*)d_in[7];
    const float* b_a  = (const float*)d_in[8];
    const float* a_a  = (const float*)d_in[9];
    const float* esc  = (const float*)d_in[10];
    float* out = (float*)d_out;

    k_meta<<<(LT + 255) / 256, 256>>>();

    int n = BB * C2C * HWN;
    k_mb<<<(n + 255) / 256, 256>>>(x, w_mb, b_mb, a_mb);

    n = BB * CC * LT;
    k_ref<<<(n + 255) / 256, 256>>>(x);

    {
        dim3 grid((LT + CT - 1) / CT, BB);
        k_convs<<<grid, 256>>>(w_m, b_m, a_m, w_a, b_a, a_a);
    }

    n = BB * LT;
    k_E<<<(n + 255) / 256, 256>>>();
    k_inv<<<(n + 255) / 256, 256>>>(esc);

    {
        dim3 grid(LPD / 64, HWN / 64, BB), block(16, 16);
        k_D<<<grid, block>>>();
    }

    k_sm<<<BB * HWN, 256>>>();

    {
        dim3 grid((LPD + 255) / 256, HWN, BB);
        k_blurA<<<grid, 256>>>();
    }

    {
        dim3 grid(HWN / 32, BB), block(16, 16);
        k_gemm2<<<grid, block>>>(x, out);
    }
}